// round 2
// baseline (speedup 1.0000x reference)
#include <cuda_runtime.h>
#include <math.h>

// Problem constants (fixed by reference)
constexpr int B = 8, C = 96, G = 64 /*PY*PX*/, J = 17, K = 96;
constexpr float WIDTH = 128.0f;

constexpr int KPT = 6;          // keypoints per thread
constexpr int KG  = K / KPT;    // 16 k-groups
constexpr int NT  = KG * J;     // 272 threads: tid = kg*17 + j

__global__ __launch_bounds__(NT, 5)
void oks_assign_kernel(const float* __restrict__ pose_pool,   // [B,C,8,8,J,2]
                       const float* __restrict__ keypoints,   // [B,K,J,3]
                       const float* __restrict__ areas,       // [B,K]
                       const float* __restrict__ transforms,  // [B,3,3]
                       const float* __restrict__ tinv,        // [B,3,3]
                       const int*   __restrict__ hflip,       // [B]
                       const float* __restrict__ sigmas,      // [J]
                       float* __restrict__ out)
{
    __shared__ float2 pose_sh[G * J];        // 8704 B: poses in image coords (packed xy)
    __shared__ float  vis_sum_sh[K];
    __shared__ float  best_sh[K * 18];       // [k][j] padded; reused as parts[G*J]
    __shared__ float  person_sh[K];
    __shared__ int    ks_sh;

    const int bc  = blockIdx.x;
    const int b   = bc / C;
    const int tid = threadIdx.x;

    // ---- Setup: inverse-affine + hflip transform of pose pool into SMEM ----
    {
        const float* Ti = tinv + b * 9;
        const float ti00 = Ti[0], ti01 = Ti[1], ti02 = Ti[2];
        const float ti10 = Ti[3], ti11 = Ti[4], ti12 = Ti[5];
        const bool flipL = hflip[b] > 0;

        const float2* pp = reinterpret_cast<const float2*>(pose_pool) + (size_t)bc * (G * J);
        for (int idx = tid; idx < G * J; idx += NT) {
            float2 p = pp[idx];
            float px = flipL ? (WIDTH - 1.0f - p.x) : p.x;
            float py = p.y;
            pose_sh[idx] = make_float2(px * ti00 + py * ti01 + ti02,
                                       px * ti10 + py * ti11 + ti12);
        }
    }

    const float* kb = keypoints + (size_t)b * K * J * 3;
    if (tid < K) {
        const float* kp = kb + (size_t)tid * J * 3;
        float s = 0.0f;
        #pragma unroll
        for (int j = 0; j < J; j++) s += (kp[j * 3 + 2] > 0.0f) ? 1.0f : 0.0f;
        vis_sum_sh[tid] = fmaxf(s, 1.0f);
    }
    __syncthreads();

    // ---- Pass A: min_g d^2 for (my j, my 6 k's) over the 64-pose grid ----
    const int j  = tid % J;
    const int kg = tid / J;
    const int k0 = kg * KPT;

    // Per-keypoint state: packed (-kx,-ky) + running min  (3 regs each)
    unsigned long long nk[KPT];
    float mind[KPT];
    #pragma unroll
    for (int i = 0; i < KPT; i++) {
        const float* kp = kb + (size_t)(k0 + i) * J * 3 + j * 3;
        float nx = -kp[0];
        float ny = -kp[1];
        asm("mov.b64 %0, {%1, %2};" : "=l"(nk[i]) : "f"(nx), "f"(ny));
        mind[i] = 3.402823466e+38f;
    }

    // Walk poses for my j: stride J float2's
    const unsigned long long* ps =
        reinterpret_cast<const unsigned long long*>(pose_sh) + j;
    #pragma unroll 2
    for (int g = 0; g < G; g++) {
        unsigned long long p = ps[g * J];   // LDS.64, addr strength-reduced by ptxas
        #pragma unroll
        for (int i = 0; i < KPT; i++) {
            unsigned long long dxy, sq;
            asm("add.rn.f32x2 %0, %1, %2;" : "=l"(dxy) : "l"(p), "l"(nk[i]));
            asm("mul.rn.f32x2 %0, %1, %1;" : "=l"(sq)  : "l"(dxy));
            float lo, hi;
            asm("mov.b64 {%0, %1}, %2;" : "=f"(lo), "=f"(hi) : "l"(sq));
            mind[i] = fminf(mind[i], lo + hi);
        }
    }

    // best[k][j] = vis * exp(-min_d / denom)
    {
        float sj   = sigmas[j] * 2.0f;
        float varj = sj * sj;
        #pragma unroll
        for (int i = 0; i < KPT; i++) {
            int k = k0 + i;
            float v     = (kb[(size_t)k * J * 3 + j * 3 + 2] > 0.0f) ? 1.0f : 0.0f;
            float denom = fmaxf(2.0f * varj * areas[b * K + k], 1e-6f);
            best_sh[k * 18 + j] = v * expf(-mind[i] / denom);
        }
    }
    __syncthreads();

    // person_best[k] = sum_j best / vis_sum
    if (tid < K) {
        float s = 0.0f;
        #pragma unroll
        for (int jj = 0; jj < J; jj++) s += best_sh[tid * 18 + jj];
        person_sh[tid] = s / vis_sum_sh[tid];
    }
    __syncthreads();

    // argmax over K (first max wins, matching jnp.argmax)
    if (tid == 0) {
        float bv = person_sh[0]; int bi = 0;
        for (int k = 1; k < K; k++) {
            float v = person_sh[k];
            if (v > bv) { bv = v; bi = k; }
        }
        ks_sh = bi;
    }
    __syncthreads();
    const int ks = ks_sh;

    // ---- Pass B: outputs for the assigned GT ks ----
    const float  area_s = areas[b * K + ks];
    const float* kpsel  = kb + (size_t)ks * J * 3;
    const bool   flip   = hflip[b] > 0;
    float* parts = best_sh;  // reuse (all best_sh readers synced above)

    float* out_parts  = out;
    float* out_person = out + (size_t)B * C * G * J;
    float* out_posegt = out_person + (size_t)B * C * G;

    for (int idx = tid; idx < G * J; idx += NT) {
        int jj = idx % J;
        float kxx = kpsel[jj * 3 + 0];
        float kyy = kpsel[jj * 3 + 1];
        float v   = (kpsel[jj * 3 + 2] > 0.0f) ? 1.0f : 0.0f;
        float s2  = sigmas[jj] * 2.0f;
        float denom = fmaxf(2.0f * s2 * s2 * area_s, 1e-6f);
        float2 p = pose_sh[idx];
        float dx = p.x - kxx, dy = p.y - kyy;
        float oks = v * expf(-fmaf(dx, dx, dy * dy) / denom);
        parts[idx] = oks;
        out_parts[(size_t)bc * (G * J) + idx] = oks;
    }
    __syncthreads();

    if (tid < G) {
        float s = 0.0f;
        #pragma unroll
        for (int jj = 0; jj < J; jj++) s += parts[tid * J + jj];
        out_person[(size_t)bc * G + tid] = s / vis_sum_sh[ks];
    }

    if (tid < J) {
        const float* t = transforms + b * 9;
        float kxx = kpsel[tid * 3 + 0];
        float kyy = kpsel[tid * 3 + 1];
        float kvv = kpsel[tid * 3 + 2];
        float gx = t[0] * kxx + t[1] * kyy + t[2];
        float gy = t[3] * kxx + t[4] * kyy + t[5];
        if (flip) gx = WIDTH - 1.0f - gx;
        float s2 = sigmas[tid] * 2.0f;
        float gv = (t[0] * t[4]) * (area_s * s2 * s2) * ((kvv > 0.0f) ? 1.0f : 0.0f);
        float* og = out_posegt + ((size_t)bc * J + tid) * 3;
        og[0] = gx; og[1] = gy; og[2] = gv;
    }
}

extern "C" void kernel_launch(void* const* d_in, const int* in_sizes, int n_in,
                              void* d_out, int out_size)
{
    const float* pose_pool  = (const float*)d_in[0];
    const float* keypoints  = (const float*)d_in[1];
    const float* areas      = (const float*)d_in[2];
    const float* transforms = (const float*)d_in[3];
    const float* tinv       = (const float*)d_in[4];
    const int*   hflip      = (const int*)  d_in[5];
    const float* sigmas     = (const float*)d_in[6];
    float* out = (float*)d_out;

    oks_assign_kernel<<<B * C, NT>>>(pose_pool, keypoints, areas, transforms,
                                     tinv, hflip, sigmas, out);
}

// round 3
// speedup vs baseline: 1.0229x; 1.0229x over previous
#include <cuda_runtime.h>
#include <math.h>

// Problem constants (fixed by reference)
constexpr int B = 8, C = 96, G = 64 /*PY*PX*/, J = 17, K = 96;
constexpr float WIDTH = 128.0f;

constexpr int KPT = 6;          // keypoints per thread
constexpr int KG  = K / KPT;    // 16 k-groups
constexpr int NT  = KG * J;     // 272 threads: tid = kg*17 + j

__global__ __launch_bounds__(NT, 6)   // force <=40 regs: 6 blocks/SM -> single wave (888 capacity > 768 blocks)
void oks_assign_kernel(const float* __restrict__ pose_pool,   // [B,C,8,8,J,2]
                       const float* __restrict__ keypoints,   // [B,K,J,3]
                       const float* __restrict__ areas,       // [B,K]
                       const float* __restrict__ transforms,  // [B,3,3]
                       const float* __restrict__ tinv,        // [B,3,3]
                       const int*   __restrict__ hflip,       // [B]
                       const float* __restrict__ sigmas,      // [J]
                       float* __restrict__ out)
{
    __shared__ float2 pose_sh[G * J];        // 8704 B: poses in image coords
    __shared__ float  vis_sum_sh[K];
    __shared__ float  best_sh[K * 18];       // [k][j] padded; reused as parts[G*J]
    __shared__ float  person_sh[K];
    __shared__ int    ks_sh;

    const int bc  = blockIdx.x;
    const int b   = bc / C;
    const int tid = threadIdx.x;

    // ---- Setup: inverse-affine + hflip transform of pose pool into SMEM ----
    {
        const float* Ti = tinv + b * 9;
        const float ti00 = Ti[0], ti01 = Ti[1], ti02 = Ti[2];
        const float ti10 = Ti[3], ti11 = Ti[4], ti12 = Ti[5];
        const bool flipL = hflip[b] > 0;

        const float2* pp = reinterpret_cast<const float2*>(pose_pool) + (size_t)bc * (G * J);
        for (int idx = tid; idx < G * J; idx += NT) {
            float2 p = pp[idx];
            float px = flipL ? (WIDTH - 1.0f - p.x) : p.x;
            float py = p.y;
            pose_sh[idx] = make_float2(px * ti00 + py * ti01 + ti02,
                                       px * ti10 + py * ti11 + ti12);
        }
    }

    const float* kb = keypoints + (size_t)b * K * J * 3;
    if (tid < K) {
        const float* kp = kb + (size_t)tid * J * 3;
        float s = 0.0f;
        #pragma unroll
        for (int j = 0; j < J; j++) s += (kp[j * 3 + 2] > 0.0f) ? 1.0f : 0.0f;
        vis_sum_sh[tid] = fmaxf(s, 1.0f);
    }
    __syncthreads();

    // ---- Pass A: min_g d^2 for (my j, my 6 k's) over the 64-pose grid ----
    const int j  = tid % J;
    const int kg = tid / J;
    const int k0 = kg * KPT;

    float kx[KPT], ky[KPT], mind[KPT];
    #pragma unroll
    for (int i = 0; i < KPT; i++) {
        const float* kp = kb + (size_t)(k0 + i) * J * 3 + j * 3;
        kx[i] = kp[0];
        ky[i] = kp[1];
        mind[i] = 3.402823466e+38f;
    }

    // Walk poses for my j: pointer stride J float2's (strength-reduced addressing)
    const float2* ps = pose_sh + j;
    #pragma unroll 4
    for (int g = 0; g < G; g++) {
        float2 p = ps[g * J];
        #pragma unroll
        for (int i = 0; i < KPT; i++) {
            float dx = p.x - kx[i];
            float dy = p.y - ky[i];
            float d  = fmaf(dx, dx, dy * dy);
            mind[i]  = fminf(mind[i], d);
        }
    }

    // best[k][j] = vis * exp(-min_d / denom)
    {
        float sj   = sigmas[j] * 2.0f;
        float varj = sj * sj;
        #pragma unroll
        for (int i = 0; i < KPT; i++) {
            int k = k0 + i;
            float v     = (kb[(size_t)k * J * 3 + j * 3 + 2] > 0.0f) ? 1.0f : 0.0f;
            float denom = fmaxf(2.0f * varj * areas[b * K + k], 1e-6f);
            best_sh[k * 18 + j] = v * expf(-mind[i] / denom);
        }
    }
    __syncthreads();

    // person_best[k] = sum_j best / vis_sum
    if (tid < K) {
        float s = 0.0f;
        #pragma unroll
        for (int jj = 0; jj < J; jj++) s += best_sh[tid * 18 + jj];
        person_sh[tid] = s / vis_sum_sh[tid];
    }
    __syncthreads();

    // argmax over K (first max wins, matching jnp.argmax)
    if (tid == 0) {
        float bv = person_sh[0]; int bi = 0;
        for (int k = 1; k < K; k++) {
            float v = person_sh[k];
            if (v > bv) { bv = v; bi = k; }
        }
        ks_sh = bi;
    }
    __syncthreads();
    const int ks = ks_sh;

    // ---- Pass B: outputs for the assigned GT ks ----
    const float  area_s = areas[b * K + ks];
    const float* kpsel  = kb + (size_t)ks * J * 3;
    const bool   flip   = hflip[b] > 0;
    float* parts = best_sh;  // reuse (all best_sh readers synced above)

    float* out_parts  = out;
    float* out_person = out + (size_t)B * C * G * J;
    float* out_posegt = out_person + (size_t)B * C * G;

    for (int idx = tid; idx < G * J; idx += NT) {
        int jj = idx % J;
        float kxx = kpsel[jj * 3 + 0];
        float kyy = kpsel[jj * 3 + 1];
        float v   = (kpsel[jj * 3 + 2] > 0.0f) ? 1.0f : 0.0f;
        float s2  = sigmas[jj] * 2.0f;
        float denom = fmaxf(2.0f * s2 * s2 * area_s, 1e-6f);
        float2 p = pose_sh[idx];
        float dx = p.x - kxx, dy = p.y - kyy;
        float oks = v * expf(-fmaf(dx, dx, dy * dy) / denom);
        parts[idx] = oks;
        out_parts[(size_t)bc * (G * J) + idx] = oks;
    }
    __syncthreads();

    if (tid < G) {
        float s = 0.0f;
        #pragma unroll
        for (int jj = 0; jj < J; jj++) s += parts[tid * J + jj];
        out_person[(size_t)bc * G + tid] = s / vis_sum_sh[ks];
    }

    if (tid < J) {
        const float* t = transforms + b * 9;
        float kxx = kpsel[tid * 3 + 0];
        float kyy = kpsel[tid * 3 + 1];
        float kvv = kpsel[tid * 3 + 2];
        float gx = t[0] * kxx + t[1] * kyy + t[2];
        float gy = t[3] * kxx + t[4] * kyy + t[5];
        if (flip) gx = WIDTH - 1.0f - gx;
        float s2 = sigmas[tid] * 2.0f;
        float gv = (t[0] * t[4]) * (area_s * s2 * s2) * ((kvv > 0.0f) ? 1.0f : 0.0f);
        float* og = out_posegt + ((size_t)bc * J + tid) * 3;
        og[0] = gx; og[1] = gy; og[2] = gv;
    }
}

extern "C" void kernel_launch(void* const* d_in, const int* in_sizes, int n_in,
                              void* d_out, int out_size)
{
    const float* pose_pool  = (const float*)d_in[0];
    const float* keypoints  = (const float*)d_in[1];
    const float* areas      = (const float*)d_in[2];
    const float* transforms = (const float*)d_in[3];
    const float* tinv       = (const float*)d_in[4];
    const int*   hflip      = (const int*)  d_in[5];
    const float* sigmas     = (const float*)d_in[6];
    float* out = (float*)d_out;

    oks_assign_kernel<<<B * C, NT>>>(pose_pool, keypoints, areas, transforms,
                                     tinv, hflip, sigmas, out);
}

// round 4
// speedup vs baseline: 1.1495x; 1.1238x over previous
#include <cuda_runtime.h>
#include <math.h>

// Problem constants (fixed by reference)
constexpr int B = 8, C = 96, G = 64 /*PY*PX*/, J = 17, K = 96;
constexpr int GP = G / 2;       // 32 pose pairs
constexpr int SJ = 33;          // float4 row stride per j (odd -> <=2-way LDS conflicts)
constexpr float WIDTH = 128.0f;

constexpr int KPT = 6;          // keypoints per thread
constexpr int KG  = K / KPT;    // 16 k-groups
constexpr int NT  = KG * J;     // 272 threads: tid = kg*17 + j

typedef unsigned long long u64;

__device__ __forceinline__ u64 pk2(float lo, float hi) {
    u64 d; asm("mov.b64 %0, {%1, %2};" : "=l"(d) : "f"(lo), "f"(hi)); return d;
}
__device__ __forceinline__ void upk2(float& lo, float& hi, u64 v) {
    asm("mov.b64 {%0, %1}, %2;" : "=f"(lo), "=f"(hi) : "l"(v));
}
__device__ __forceinline__ u64 add2(u64 a, u64 b) {
    u64 d; asm("add.rn.f32x2 %0, %1, %2;" : "=l"(d) : "l"(a), "l"(b)); return d;
}
__device__ __forceinline__ u64 mul2(u64 a, u64 b) {
    u64 d; asm("mul.rn.f32x2 %0, %1, %2;" : "=l"(d) : "l"(a), "l"(b)); return d;
}
__device__ __forceinline__ u64 fma2(u64 a, u64 b, u64 c) {
    u64 d; asm("fma.rn.f32x2 %0, %1, %2, %3;" : "=l"(d) : "l"(a), "l"(b), "l"(c)); return d;
}

__global__ __launch_bounds__(NT, 4)
void oks_assign_kernel(const float* __restrict__ pose_pool,   // [B,C,8,8,J,2]
                       const float* __restrict__ keypoints,   // [B,K,J,3]
                       const float* __restrict__ areas,       // [B,K]
                       const float* __restrict__ transforms,  // [B,3,3]
                       const float* __restrict__ tinv,        // [B,3,3]
                       const int*   __restrict__ hflip,       // [B]
                       const float* __restrict__ sigmas,      // [J]
                       float* __restrict__ out)
{
    __shared__ float4 posep_sh[J * SJ];      // (x_g0,x_g1,y_g0,y_g1) per (j, g-pair)
    __shared__ float  vis_sum_sh[K];
    __shared__ float  best_sh[K * 18];       // [k][j] padded; reused as parts[G*J]
    __shared__ float  person_sh[K];
    __shared__ int    ks_sh;

    const int bc  = blockIdx.x;
    const int b   = bc / C;
    const int tid = threadIdx.x;

    // ---- Setup: inverse-affine + hflip; store pose pairs (g0,g1) per lane ----
    {
        const float* Ti = tinv + b * 9;
        const float ti00 = Ti[0], ti01 = Ti[1], ti02 = Ti[2];
        const float ti10 = Ti[3], ti11 = Ti[4], ti12 = Ti[5];
        const bool flipL = hflip[b] > 0;

        const float2* pp = reinterpret_cast<const float2*>(pose_pool) + (size_t)bc * (G * J);
        for (int idx = tid; idx < J * GP; idx += NT) {
            int gp = idx / J;
            int j  = idx % J;
            float2 a = pp[(2 * gp) * J + j];
            float2 c = pp[(2 * gp + 1) * J + j];
            float ax = flipL ? (WIDTH - 1.0f - a.x) : a.x;
            float cx = flipL ? (WIDTH - 1.0f - c.x) : c.x;
            float ay = a.y, cy = c.y;
            float x0 = ax * ti00 + ay * ti01 + ti02;
            float y0 = ax * ti10 + ay * ti11 + ti12;
            float x1 = cx * ti00 + cy * ti01 + ti02;
            float y1 = cx * ti10 + cy * ti11 + ti12;
            posep_sh[j * SJ + gp] = make_float4(x0, x1, y0, y1);
        }
    }

    const float* kb = keypoints + (size_t)b * K * J * 3;
    if (tid < K) {
        const float* kp = kb + (size_t)tid * J * 3;
        float s = 0.0f;
        #pragma unroll
        for (int j = 0; j < J; j++) s += (kp[j * 3 + 2] > 0.0f) ? 1.0f : 0.0f;
        vis_sum_sh[tid] = fmaxf(s, 1.0f);
    }
    __syncthreads();

    // ---- Pass A: min_g d^2 for (my j, my 6 k's), two g's per packed op ----
    const int j  = tid % J;
    const int kg = tid / J;
    const int k0 = kg * KPT;

    u64   nkx[KPT], nky[KPT];
    float mind[KPT];
    #pragma unroll
    for (int i = 0; i < KPT; i++) {
        const float* kp = kb + (size_t)(k0 + i) * J * 3 + j * 3;
        float nx = -kp[0];
        float ny = -kp[1];
        nkx[i] = pk2(nx, nx);
        nky[i] = pk2(ny, ny);
        mind[i] = 3.402823466e+38f;
    }

    const float4* prow = posep_sh + j * SJ;
    #pragma unroll 4
    for (int gp = 0; gp < GP; gp++) {
        float4 p4 = prow[gp];               // LDS.128: (x0,x1,y0,y1)
        u64 pxp = pk2(p4.x, p4.y);          // free: adjacent reg pair
        u64 pyp = pk2(p4.z, p4.w);
        #pragma unroll
        for (int i = 0; i < KPT; i++) {
            u64 dx = add2(pxp, nkx[i]);     // lanewise == scalar FADD
            u64 dy = add2(pyp, nky[i]);
            u64 s  = mul2(dy, dy);
            u64 d  = fma2(dx, dx, s);       // lanewise == scalar FFMA
            float dlo, dhi;
            upk2(dlo, dhi, d);              // free
            mind[i] = fminf(mind[i], dlo);
            mind[i] = fminf(mind[i], dhi);
        }
    }

    // best[k][j] = vis * exp(-min_d / denom)
    {
        float sj   = sigmas[j] * 2.0f;
        float varj = sj * sj;
        #pragma unroll
        for (int i = 0; i < KPT; i++) {
            int k = k0 + i;
            float v     = (kb[(size_t)k * J * 3 + j * 3 + 2] > 0.0f) ? 1.0f : 0.0f;
            float denom = fmaxf(2.0f * varj * areas[b * K + k], 1e-6f);
            best_sh[k * 18 + j] = v * expf(-mind[i] / denom);
        }
    }
    __syncthreads();

    // person_best[k] = sum_j best / vis_sum
    if (tid < K) {
        float s = 0.0f;
        #pragma unroll
        for (int jj = 0; jj < J; jj++) s += best_sh[tid * 18 + jj];
        person_sh[tid] = s / vis_sum_sh[tid];
    }
    __syncthreads();

    // argmax over K (first max wins, matching jnp.argmax)
    if (tid == 0) {
        float bv = person_sh[0]; int bi = 0;
        for (int k = 1; k < K; k++) {
            float v = person_sh[k];
            if (v > bv) { bv = v; bi = k; }
        }
        ks_sh = bi;
    }
    __syncthreads();
    const int ks = ks_sh;

    // ---- Pass B: outputs for the assigned GT ks ----
    const float  area_s = areas[b * K + ks];
    const float* kpsel  = kb + (size_t)ks * J * 3;
    const bool   flip   = hflip[b] > 0;
    float* parts = best_sh;  // reuse (all best_sh readers synced above)

    float* out_parts  = out;
    float* out_person = out + (size_t)B * C * G * J;
    float* out_posegt = out_person + (size_t)B * C * G;

    for (int idx = tid; idx < G * J; idx += NT) {
        int g  = idx / J;
        int jj = idx % J;
        float kxx = kpsel[jj * 3 + 0];
        float kyy = kpsel[jj * 3 + 1];
        float v   = (kpsel[jj * 3 + 2] > 0.0f) ? 1.0f : 0.0f;
        float s2  = sigmas[jj] * 2.0f;
        float denom = fmaxf(2.0f * s2 * s2 * area_s, 1e-6f);
        float4 f4 = posep_sh[jj * SJ + (g >> 1)];
        float px = (g & 1) ? f4.y : f4.x;
        float py = (g & 1) ? f4.w : f4.z;
        float dx = px - kxx, dy = py - kyy;
        float oks = v * expf(-fmaf(dx, dx, dy * dy) / denom);
        parts[idx] = oks;
        out_parts[(size_t)bc * (G * J) + idx] = oks;
    }
    __syncthreads();

    if (tid < G) {
        float s = 0.0f;
        #pragma unroll
        for (int jj = 0; jj < J; jj++) s += parts[tid * J + jj];
        out_person[(size_t)bc * G + tid] = s / vis_sum_sh[ks];
    }

    if (tid < J) {
        const float* t = transforms + b * 9;
        float kxx = kpsel[tid * 3 + 0];
        float kyy = kpsel[tid * 3 + 1];
        float kvv = kpsel[tid * 3 + 2];
        float gx = t[0] * kxx + t[1] * kyy + t[2];
        float gy = t[3] * kxx + t[4] * kyy + t[5];
        if (flip) gx = WIDTH - 1.0f - gx;
        float s2 = sigmas[tid] * 2.0f;
        float gv = (t[0] * t[4]) * (area_s * s2 * s2) * ((kvv > 0.0f) ? 1.0f : 0.0f);
        float* og = out_posegt + ((size_t)bc * J + tid) * 3;
        og[0] = gx; og[1] = gy; og[2] = gv;
    }
}

extern "C" void kernel_launch(void* const* d_in, const int* in_sizes, int n_in,
                              void* d_out, int out_size)
{
    const float* pose_pool  = (const float*)d_in[0];
    const float* keypoints  = (const float*)d_in[1];
    const float* areas      = (const float*)d_in[2];
    const float* transforms = (const float*)d_in[3];
    const float* tinv       = (const float*)d_in[4];
    const int*   hflip      = (const int*)  d_in[5];
    const float* sigmas     = (const float*)d_in[6];
    float* out = (float*)d_out;

    oks_assign_kernel<<<B * C, NT>>>(pose_pool, keypoints, areas, transforms,
                                     tinv, hflip, sigmas, out);
}

// round 5
// speedup vs baseline: 1.1631x; 1.0118x over previous
#include <cuda_runtime.h>
#include <math.h>

// Problem constants (fixed by reference)
constexpr int B = 8, C = 96, G = 64 /*PY*PX*/, J = 17, K = 96;
constexpr int GP = G / 2;       // 32 pose pairs
constexpr int SJ = 33;          // float4 row stride per j (odd -> low LDS conflicts)
constexpr float WIDTH = 128.0f;

constexpr int KPT = 6;          // keypoints per thread
constexpr int KG  = K / KPT;    // 16 k-groups
constexpr int NT  = KG * J;     // 272 threads: tid = kg*17 + j

typedef unsigned long long u64;

__device__ __forceinline__ u64 pk2(float lo, float hi) {
    u64 d; asm("mov.b64 %0, {%1, %2};" : "=l"(d) : "f"(lo), "f"(hi)); return d;
}
__device__ __forceinline__ void upk2(float& lo, float& hi, u64 v) {
    asm("mov.b64 {%0, %1}, %2;" : "=f"(lo), "=f"(hi) : "l"(v));
}
__device__ __forceinline__ u64 add2(u64 a, u64 b) {
    u64 d; asm("add.rn.f32x2 %0, %1, %2;" : "=l"(d) : "l"(a), "l"(b)); return d;
}
__device__ __forceinline__ u64 mul2(u64 a, u64 b) {
    u64 d; asm("mul.rn.f32x2 %0, %1, %2;" : "=l"(d) : "l"(a), "l"(b)); return d;
}
__device__ __forceinline__ u64 fma2(u64 a, u64 b, u64 c) {
    u64 d; asm("fma.rn.f32x2 %0, %1, %2, %3;" : "=l"(d) : "l"(a), "l"(b), "l"(c)); return d;
}

__global__ __launch_bounds__(NT, 4)
void oks_assign_kernel(const float* __restrict__ pose_pool,   // [B,C,8,8,J,2]
                       const float* __restrict__ keypoints,   // [B,K,J,3]
                       const float* __restrict__ areas,       // [B,K]
                       const float* __restrict__ transforms,  // [B,3,3]
                       const float* __restrict__ tinv,        // [B,3,3]
                       const int*   __restrict__ hflip,       // [B]
                       const float* __restrict__ sigmas,      // [J]
                       float* __restrict__ out)
{
    __shared__ float4 posep_sh[J * SJ];      // (x_g0,x_g1,y_g0,y_g1) per (j, g-pair)
    __shared__ float  vis_sum_sh[K];
    __shared__ float  best_sh[K * 18];       // [k][j] padded; reused as parts[G*J]
    __shared__ float  person_sh[K];
    __shared__ int    ks_sh;

    const int bc  = blockIdx.x;
    const int b   = bc / C;
    const int tid = threadIdx.x;

    // ---- Setup: inverse-affine + hflip; store pose pairs (g0,g1) per lane ----
    {
        const float* Ti = tinv + b * 9;
        const float ti00 = Ti[0], ti01 = Ti[1], ti02 = Ti[2];
        const float ti10 = Ti[3], ti11 = Ti[4], ti12 = Ti[5];
        const bool flipL = hflip[b] > 0;

        const float2* pp = reinterpret_cast<const float2*>(pose_pool) + (size_t)bc * (G * J);
        for (int idx = tid; idx < J * GP; idx += NT) {
            int gp = idx / J;
            int j  = idx % J;
            float2 a = pp[(2 * gp) * J + j];
            float2 c = pp[(2 * gp + 1) * J + j];
            float ax = flipL ? (WIDTH - 1.0f - a.x) : a.x;
            float cx = flipL ? (WIDTH - 1.0f - c.x) : c.x;
            float ay = a.y, cy = c.y;
            float x0 = ax * ti00 + ay * ti01 + ti02;
            float y0 = ax * ti10 + ay * ti11 + ti12;
            float x1 = cx * ti00 + cy * ti01 + ti02;
            float y1 = cx * ti10 + cy * ti11 + ti12;
            posep_sh[j * SJ + gp] = make_float4(x0, x1, y0, y1);
        }
    }

    const float* kb = keypoints + (size_t)b * K * J * 3;
    if (tid < K) {
        const float* kp = kb + (size_t)tid * J * 3;
        float s = 0.0f;
        #pragma unroll
        for (int j = 0; j < J; j++) s += (kp[j * 3 + 2] > 0.0f) ? 1.0f : 0.0f;
        vis_sum_sh[tid] = fmaxf(s, 1.0f);
    }
    __syncthreads();

    // ---- Pass A: min_g d^2 for (my j, my 6 k's), two g's per packed op ----
    const int j  = tid % J;
    const int kg = tid / J;
    const int k0 = kg * KPT;

    u64   nkx[KPT], nky[KPT];
    float mind_lo[KPT], mind_hi[KPT];
    #pragma unroll
    for (int i = 0; i < KPT; i++) {
        const float* kp = kb + (size_t)(k0 + i) * J * 3 + j * 3;
        float nx = -kp[0];
        float ny = -kp[1];
        nkx[i] = pk2(nx, nx);
        nky[i] = pk2(ny, ny);
        mind_lo[i] = 3.402823466e+38f;
        mind_hi[i] = 3.402823466e+38f;
    }

    const float4* prow = posep_sh + j * SJ;
    #pragma unroll 8
    for (int gp = 0; gp < GP; gp++) {
        float4 p4 = prow[gp];               // LDS.128: (x0,x1,y0,y1)
        u64 pxp = pk2(p4.x, p4.y);          // adjacent reg pair
        u64 pyp = pk2(p4.z, p4.w);
        #pragma unroll
        for (int i = 0; i < KPT; i++) {
            u64 dx = add2(pxp, nkx[i]);     // lanewise == scalar FADD
            u64 dy = add2(pyp, nky[i]);
            u64 s  = mul2(dy, dy);
            u64 d  = fma2(dx, dx, s);       // lanewise == scalar FFMA
            float dlo, dhi;
            upk2(dlo, dhi, d);
            mind_lo[i] = fminf(mind_lo[i], dlo);   // two independent chains
            mind_hi[i] = fminf(mind_hi[i], dhi);
        }
    }

    // best[k][j] = vis * exp(-min_d / denom)   (accurate expf: feeds argmax)
    {
        float sj   = sigmas[j] * 2.0f;
        float varj = sj * sj;
        #pragma unroll
        for (int i = 0; i < KPT; i++) {
            int k = k0 + i;
            float md    = fminf(mind_lo[i], mind_hi[i]);
            float v     = (kb[(size_t)k * J * 3 + j * 3 + 2] > 0.0f) ? 1.0f : 0.0f;
            float denom = fmaxf(2.0f * varj * areas[b * K + k], 1e-6f);
            best_sh[k * 18 + j] = v * expf(-md / denom);
        }
    }
    __syncthreads();

    // person_best[k] = sum_j best / vis_sum
    if (tid < K) {
        float s = 0.0f;
        #pragma unroll
        for (int jj = 0; jj < J; jj++) s += best_sh[tid * 18 + jj];
        person_sh[tid] = s / vis_sum_sh[tid];
    }
    __syncthreads();

    // Warp-parallel argmax over K (first max wins, matching jnp.argmax)
    if (tid < 32) {
        float bv = -1.0f; int bi = 0;
        #pragma unroll
        for (int r = 0; r < 3; r++) {          // k = tid, tid+32, tid+64 (ascending)
            int k = tid + r * 32;
            float v = person_sh[k];
            if (v > bv) { bv = v; bi = k; }
        }
        #pragma unroll
        for (int off = 16; off > 0; off >>= 1) {
            float ov = __shfl_xor_sync(0xFFFFFFFFu, bv, off);
            int   oi = __shfl_xor_sync(0xFFFFFFFFu, bi, off);
            if (ov > bv || (ov == bv && oi < bi)) { bv = ov; bi = oi; }
        }
        if (tid == 0) ks_sh = bi;
    }
    __syncthreads();
    const int ks = ks_sh;

    // ---- Pass B: outputs for the assigned GT ks ----
    const float  area_s = areas[b * K + ks];
    const float* kpsel  = kb + (size_t)ks * J * 3;
    const bool   flip   = hflip[b] > 0;
    float* parts = best_sh;  // reuse (all best_sh readers synced above)

    float* out_parts  = out;
    float* out_person = out + (size_t)B * C * G * J;
    float* out_posegt = out_person + (size_t)B * C * G;

    for (int idx = tid; idx < G * J; idx += NT) {
        int g  = idx / J;
        int jj = idx % J;
        float kxx = kpsel[jj * 3 + 0];
        float kyy = kpsel[jj * 3 + 1];
        float v   = (kpsel[jj * 3 + 2] > 0.0f) ? 1.0f : 0.0f;
        float s2  = sigmas[jj] * 2.0f;
        float denom = fmaxf(2.0f * s2 * s2 * area_s, 1e-6f);
        float4 f4 = posep_sh[jj * SJ + (g >> 1)];
        float px = (g & 1) ? f4.y : f4.x;
        float py = (g & 1) ? f4.w : f4.z;
        float dx = px - kxx, dy = py - kyy;
        // __expf: ~2e-6 rel err, only feeds outputs (1e-3 tol), not the argmax
        float oks = v * __expf(-fmaf(dx, dx, dy * dy) / denom);
        parts[idx] = oks;
        out_parts[(size_t)bc * (G * J) + idx] = oks;
    }
    __syncthreads();

    if (tid < G) {
        float s = 0.0f;
        #pragma unroll
        for (int jj = 0; jj < J; jj++) s += parts[tid * J + jj];
        out_person[(size_t)bc * G + tid] = s / vis_sum_sh[ks];
    }

    if (tid < J) {
        const float* t = transforms + b * 9;
        float kxx = kpsel[tid * 3 + 0];
        float kyy = kpsel[tid * 3 + 1];
        float kvv = kpsel[tid * 3 + 2];
        float gx = t[0] * kxx + t[1] * kyy + t[2];
        float gy = t[3] * kxx + t[4] * kyy + t[5];
        if (flip) gx = WIDTH - 1.0f - gx;
        float s2 = sigmas[tid] * 2.0f;
        float gv = (t[0] * t[4]) * (area_s * s2 * s2) * ((kvv > 0.0f) ? 1.0f : 0.0f);
        float* og = out_posegt + ((size_t)bc * J + tid) * 3;
        og[0] = gx; og[1] = gy; og[2] = gv;
    }
}

extern "C" void kernel_launch(void* const* d_in, const int* in_sizes, int n_in,
                              void* d_out, int out_size)
{
    const float* pose_pool  = (const float*)d_in[0];
    const float* keypoints  = (const float*)d_in[1];
    const float* areas      = (const float*)d_in[2];
    const float* transforms = (const float*)d_in[3];
    const float* tinv       = (const float*)d_in[4];
    const int*   hflip      = (const int*)  d_in[5];
    const float* sigmas     = (const float*)d_in[6];
    float* out = (float*)d_out;

    oks_assign_kernel<<<B * C, NT>>>(pose_pool, keypoints, areas, transforms,
                                     tinv, hflip, sigmas, out);
}